// round 1
// baseline (speedup 1.0000x reference)
#include <cuda_runtime.h>
#include <math.h>

// Accumulators: 0 focal_fs, 1 focal_ss, 2 iou_fs, 3 iou_ss, 4 cnt_fs, 5 cnt_ss
__device__ double g_acc[6];

#define MAXK 128
#define BLOCK 256

__global__ void zero_acc_kernel() {
    if (threadIdx.x < 6) g_acc[threadIdx.x] = 0.0;
}

__device__ __forceinline__ float focal_term(float l, float t) {
    // stable BCE-with-logits
    float ce = fmaxf(l, 0.f) - l * t + log1pf(expf(-fabsf(l)));
    float p  = 1.f / (1.f + expf(-l));
    float pt = p * t + (1.f - p) * (1.f - t);
    float at = 0.25f * t + 0.75f * (1.f - t);
    float m  = 1.f - pt;
    return at * ce * m * m;
}

// IoU of pred box (xywh) vs gt box (xyxy, precomputed area)
__device__ __forceinline__ float pred_iou(float px, float py, float pw, float ph,
                                          float4 g, float garea) {
    float px2 = px + pw, py2 = py + ph;
    float lx = fmaxf(px, g.x), ly = fmaxf(py, g.y);
    float rx = fminf(px2, g.z), ry = fminf(py2, g.w);
    float w = fmaxf(rx - lx, 0.f), h = fmaxf(ry - ly, 0.f);
    float inter = w * h;
    float pa = pw * ph;
    return __fdividef(inter, pa + garea - inter);
}

__global__ __launch_bounds__(BLOCK)
void ainno_main_kernel(const float* __restrict__ fs,
                       const float* __restrict__ ss,
                       const float* __restrict__ anchors,
                       const float* __restrict__ gt,
                       int B, int C, int K)
{
    __shared__ float4 s_gbox[MAXK];   // gt xyxy
    __shared__ float  s_garea[MAXK];  // gt area
    __shared__ float  s_red[6][BLOCK / 32];

    const int tid = threadIdx.x;
    const int b   = blockIdx.y;

    if (tid < K) {
        const float* g = gt + ((size_t)b * K + tid) * 4;
        float x = g[0], y = g[1], w = g[2], h = g[3];
        s_gbox[tid]  = make_float4(x, y, x + w, y + h);
        s_garea[tid] = w * h;
    }
    __syncthreads();

    const int c = blockIdx.x * BLOCK + tid;

    float acc_f_fs = 0.f, acc_f_ss = 0.f;
    float acc_l_fs = 0.f, acc_l_ss = 0.f;
    float acc_c_fs = 0.f, acc_c_ss = 0.f;

    if (c < C) {
        // anchors is (C,4) f32, 16B-aligned rows
        float4 a = *(const float4*)(anchors + (size_t)c * 4);
        float ax1 = a.x, ay1 = a.y, ax2 = a.x + a.z, ay2 = a.y + a.w;
        float area_a = a.z * a.w;

        // argmax IoU via cross-multiplied comparison (no per-pair divide).
        // Strict > keeps the FIRST max index, matching jnp.argmax.
        float best_i = 0.f, best_u = 1.f;
        int   best_k = 0;
        #pragma unroll 8
        for (int i = 0; i < K; i++) {
            float4 g = s_gbox[i];
            float lx = fmaxf(ax1, g.x), ly = fmaxf(ay1, g.y);
            float rx = fminf(ax2, g.z), ry = fminf(ay2, g.w);
            float w  = fmaxf(rx - lx, 0.f);
            float h  = fmaxf(ry - ly, 0.f);
            float inter = w * h;
            float uni   = area_a + s_garea[i] - inter;
            if (inter * best_u > best_i * uni) {
                best_i = inter; best_u = uni; best_k = i;
            }
        }
        float ts = __fdividef(best_i, best_u);  // 0 when no overlap

        // proposal rows are 6 floats (24B stride) -> only 8B-aligned: use float2
        size_t base = ((size_t)b * C + c) * 6;
        float2 f0 = *(const float2*)(fs + base);
        float2 f1 = *(const float2*)(fs + base + 2);
        float2 f2 = *(const float2*)(fs + base + 4);
        float2 s0 = *(const float2*)(ss + base);
        float2 s1 = *(const float2*)(ss + base + 2);
        float2 s2 = *(const float2*)(ss + base + 4);

        acc_f_fs = focal_term(f2.x, ts);
        acc_f_ss = focal_term(s2.x, ts);

        if (ts >= 0.5f) {
            float4 g = s_gbox[best_k];
            float ga = s_garea[best_k];
            acc_c_ss = 1.f;
            acc_l_ss = -logf(pred_iou(s0.x, s0.y, s1.x, s1.y, g, ga));
            if (ts >= 0.7f) {
                acc_c_fs = 1.f;
                acc_l_fs = -logf(pred_iou(f0.x, f0.y, f1.x, f1.y, g, ga));
            }
        }
    }

    // ---- block reduction of 6 scalars ----
    float v[6] = {acc_f_fs, acc_f_ss, acc_l_fs, acc_l_ss, acc_c_fs, acc_c_ss};
    #pragma unroll
    for (int j = 0; j < 6; j++) {
        float x = v[j];
        #pragma unroll
        for (int off = 16; off > 0; off >>= 1)
            x += __shfl_down_sync(0xFFFFFFFFu, x, off);
        v[j] = x;
    }
    int warp = tid >> 5, lane = tid & 31;
    if (lane == 0) {
        #pragma unroll
        for (int j = 0; j < 6; j++) s_red[j][warp] = v[j];
    }
    __syncthreads();
    if (warp == 0) {
        const int nw = BLOCK / 32;
        #pragma unroll
        for (int j = 0; j < 6; j++) {
            float x = (lane < nw) ? s_red[j][lane] : 0.f;
            #pragma unroll
            for (int off = 4; off > 0; off >>= 1)
                x += __shfl_down_sync(0xFFFFFFFFu, x, off);
            if (lane == 0) atomicAdd(&g_acc[j], (double)x);
        }
    }
}

__global__ void finalize_kernel(float* __restrict__ out, int B, int C) {
    if (threadIdx.x != 0 || blockIdx.x != 0) return;
    double N      = (double)B * (double)C;
    double cnt_fs = g_acc[4] < 1.0 ? 1.0 : g_acc[4];
    double cnt_ss = g_acc[5] < 1.0 ? 1.0 : g_acc[5];
    double res = (g_acc[1] / N) / cnt_ss   // ss_stc
               + (g_acc[0] / N) / cnt_fs   // fs_stc
               + (g_acc[3] / cnt_ss)       // ss_str
               + (g_acc[2] / cnt_fs);      // fs_str
    out[0] = (float)res;
}

extern "C" void kernel_launch(void* const* d_in, const int* in_sizes, int n_in,
                              void* d_out, int out_size) {
    const float* fs      = (const float*)d_in[0];
    const float* ss      = (const float*)d_in[1];
    const float* anchors = (const float*)d_in[2];
    const float* gt      = (const float*)d_in[3];
    float* out = (float*)d_out;

    int C = in_sizes[2] / 4;
    int B = in_sizes[0] / (6 * C);
    int K = in_sizes[3] / (4 * B);

    zero_acc_kernel<<<1, 32>>>();
    dim3 grid((C + BLOCK - 1) / BLOCK, B);
    ainno_main_kernel<<<grid, BLOCK>>>(fs, ss, anchors, gt, B, C, K);
    finalize_kernel<<<1, 32>>>(out, B, C);
}